// round 2
// baseline (speedup 1.0000x reference)
#include <cuda_runtime.h>
#include <cuda_bf16.h>
#include <math.h>

#define N 192
#define C 256
#define K 16
#define P_COUNT 2304      // K * (N/K)^2
#define NEG_COUNT 34560   // N*N - P_COUNT
#define MARGIN 0.05f
#define EPS 1e-6f

// Scratch (device globals: allocation is forbidden)
__device__ float g_p[P_COUNT];
__device__ float g_n[NEG_COUNT];
__device__ float g_ssq[N];
__device__ int   g_preCnt[K * N];   // preCnt[L][j] = #{j' < j : tgt[j'] == L}
__device__ int   g_posOff[N];       // posOff[i]   = # positive pairs in rows < i

// ---------------------------------------------------------------------------
// Kernel A: norms^2, per-label prefix counts, positive-offset table.
// One block, 256 threads. posOff via closed form (no serial scan):
//   posOff[i] = sum_L total[L] * preCnt[L][i]
// ---------------------------------------------------------------------------
__global__ void setup_kernel(const float* __restrict__ pred,
                             const int* __restrict__ target) {
    const int tid  = threadIdx.x;
    const int wid  = tid >> 5;
    const int lane = tid & 31;

    __shared__ int tgt[N];
    __shared__ int s_pre[K][N];
    __shared__ int s_total[K];

    for (int t = tid; t < N; t += 256) tgt[t] = target[t];

    // norms^2: 8 warps, warp handles rows wid, wid+8, ...
    for (int i = wid; i < N; i += 8) {
        const float4* pr = (const float4*)(pred + i * C);
        float4 a = pr[lane * 2];
        float4 b = pr[lane * 2 + 1];
        float ss = a.x * a.x + a.y * a.y + a.z * a.z + a.w * a.w
                 + b.x * b.x + b.y * b.y + b.z * b.z + b.w * b.w;
        #pragma unroll
        for (int off = 16; off > 0; off >>= 1)
            ss += __shfl_xor_sync(0xFFFFFFFFu, ss, off);
        if (lane == 0) g_ssq[i] = ss;
    }
    __syncthreads();

    // per-label prefix counts (16 parallel serial scans of length 192)
    if (tid < K) {
        int c = 0;
        for (int j = 0; j < N; j++) {
            s_pre[tid][j] = c;
            g_preCnt[tid * N + j] = c;
            c += (tgt[j] == tid) ? 1 : 0;
        }
        s_total[tid] = c;
    }
    __syncthreads();

    // posOff[i] = sum_L total[L] * preCnt[L][i]
    if (tid < N) {
        int po = 0;
        #pragma unroll
        for (int L = 0; L < K; L++) po += s_total[L] * s_pre[L][tid];
        g_posOff[tid] = po;
    }
}

// ---------------------------------------------------------------------------
// Kernel B: cosine distance + ordered scatter. Block = row i, thread = col j.
// No shuffles, no serial sections: per-thread serial dot (rowi from smem,
// rowj via LDG.128 pairs -> full 32B sector utilization), table-lookup rank.
// ---------------------------------------------------------------------------
__global__ __launch_bounds__(192, 8)
void dist_scatter_kernel(const float* __restrict__ pred,
                         const int* __restrict__ target) {
    const int i = blockIdx.x;
    const int j = threadIdx.x;

    __shared__ float4 rowi[C / 4];

    const float4* pi4 = (const float4*)(pred + i * C);
    if (j < C / 4) rowi[j] = pi4[j];
    __syncthreads();

    // broadcast loads (same address across the block -> single transaction)
    const int   Li  = target[i];
    const float ssi = g_ssq[i];
    const int   po  = g_posOff[i];

    const float4* pj4 = (const float4*)(pred + j * C);
    float d0 = 0.f, d1 = 0.f, d2 = 0.f, d3 = 0.f;
    #pragma unroll 16
    for (int q = 0; q < C / 4; q += 4) {
        float4 a0 = pj4[q],     r0 = rowi[q];
        float4 a1 = pj4[q + 1], r1 = rowi[q + 1];
        float4 a2 = pj4[q + 2], r2 = rowi[q + 2];
        float4 a3 = pj4[q + 3], r3 = rowi[q + 3];
        d0 += a0.x * r0.x + a0.y * r0.y + a0.z * r0.z + a0.w * r0.w;
        d1 += a1.x * r1.x + a1.y * r1.y + a1.z * r1.z + a1.w * r1.w;
        d2 += a2.x * r2.x + a2.y * r2.y + a2.z * r2.z + a2.w * r2.w;
        d3 += a3.x * r3.x + a3.y * r3.y + a3.z * r3.z + a3.w * r3.w;
    }
    const float dot = (d0 + d1) + (d2 + d3);

    const float ssj   = g_ssq[j];
    const float denom = fmaxf(sqrtf(ssi * ssj), EPS);
    const float dist  = 0.5f - 0.5f * dot / denom;

    const int Lj  = target[j];
    const int pre = g_preCnt[Li * N + j];   // #{j' < j : tgt[j'] == Li}
    if (Lj == Li) {
        g_p[po + pre] = dist;
    } else {
        g_n[i * N - po + (j - pre)] = dist;
    }
}

// ---------------------------------------------------------------------------
// Kernel C: out[m][k] = max(0, MARGIN + p[k] - n[m])  (34560 x 2304 fp32).
// Persistent grid-stride over rows m (grid = 1184 = 148 SMs x 8 blocks):
// no wave tail, p pinned in registers, rolling prefetch of n, float4
// streaming stores.
// ---------------------------------------------------------------------------
#define T2 192
#define GRID2 1184

__global__ __launch_bounds__(T2, 8)
void outer_kernel(float* __restrict__ out) {
    const int tid    = threadIdx.x;
    const int stride = gridDim.x;

    const float4* p4 = (const float4*)g_p;
    const float4 pv0 = p4[tid];
    const float4 pv1 = p4[tid + 192];
    const float4 pv2 = p4[tid + 384];

    int m = blockIdx.x;
    float nv = (m < NEG_COUNT) ? g_n[m] : 0.f;

    for (; m < NEG_COUNT; m += stride) {
        const int mn = m + stride;
        const float nnext = (mn < NEG_COUNT) ? g_n[mn] : 0.f;

        const float c = MARGIN - nv;
        float4* o = (float4*)(out + (size_t)m * P_COUNT);

        float4 w0, w1, w2;
        w0.x = fmaxf(0.f, pv0.x + c); w0.y = fmaxf(0.f, pv0.y + c);
        w0.z = fmaxf(0.f, pv0.z + c); w0.w = fmaxf(0.f, pv0.w + c);
        w1.x = fmaxf(0.f, pv1.x + c); w1.y = fmaxf(0.f, pv1.y + c);
        w1.z = fmaxf(0.f, pv1.z + c); w1.w = fmaxf(0.f, pv1.w + c);
        w2.x = fmaxf(0.f, pv2.x + c); w2.y = fmaxf(0.f, pv2.y + c);
        w2.z = fmaxf(0.f, pv2.z + c); w2.w = fmaxf(0.f, pv2.w + c);

        __stcs(&o[tid],       w0);
        __stcs(&o[tid + 192], w1);
        __stcs(&o[tid + 384], w2);

        nv = nnext;
    }
}

extern "C" void kernel_launch(void* const* d_in, const int* in_sizes, int n_in,
                              void* d_out, int out_size) {
    const float* pred   = (const float*)d_in[0];
    const int*   target = (const int*)d_in[1];
    float*       out    = (float*)d_out;

    setup_kernel<<<1, 256>>>(pred, target);
    dist_scatter_kernel<<<N, 192>>>(pred, target);
    outer_kernel<<<GRID2, T2>>>(out);
}